// round 10
// baseline (speedup 1.0000x reference)
#include <cuda_runtime.h>
#include <cuda_fp16.h>
#include <cstdint>

#define DD 128
#define TT 64
#define NPOW 9           // A^0 .. A^8 (Taylor K=8; tail ~1e-5 relative)
#define BB 8192

// ---------------- device scratch (no allocs allowed) ----------------
__device__ __align__(1024) float g_Wp[NPOW][DD * DD];   // A^k, A = dt*W
__device__ __align__(1024) __half g_Bf[TT][DD * DD];    // P_t fp16, row-major [k][n]
__device__ __align__(1024) __half g_xh[BB * DD];        // x fp16
__device__ int g_bar[4];                                // grid-barrier counters

// ---------------- helpers ----------------
__device__ __forceinline__ uint32_t smem_u32(const void* p) {
    uint32_t a;
    asm("{ .reg .u64 t; cvta.to.shared.u64 t, %1; cvt.u32.u64 %0, t; }" : "=r"(a) : "l"(p));
    return a;
}
__device__ __forceinline__ void ldsm4(uint32_t* r, uint32_t a) {
    asm volatile("ldmatrix.sync.aligned.m8n8.x4.shared.b16 {%0,%1,%2,%3}, [%4];"
                 : "=r"(r[0]), "=r"(r[1]), "=r"(r[2]), "=r"(r[3]) : "r"(a));
}
__device__ __forceinline__ void ldsm4t(uint32_t* r, uint32_t a) {
    asm volatile("ldmatrix.sync.aligned.m8n8.x4.trans.shared.b16 {%0,%1,%2,%3}, [%4];"
                 : "=r"(r[0]), "=r"(r[1]), "=r"(r[2]), "=r"(r[3]) : "r"(a));
}
__device__ __forceinline__ void mma16816(float* d, const uint32_t* a,
                                         uint32_t b0, uint32_t b1) {
    asm volatile(
        "mma.sync.aligned.m16n8k16.row.col.f32.f16.f16.f32 "
        "{%0,%1,%2,%3}, {%4,%5,%6,%7}, {%8,%9}, {%0,%1,%2,%3};"
        : "+f"(d[0]), "+f"(d[1]), "+f"(d[2]), "+f"(d[3])
        : "r"(a[0]), "r"(a[1]), "r"(a[2]), "r"(a[3]), "r"(b0), "r"(b1));
}
__device__ __forceinline__ void cp16(uint32_t dst, const void* src) {
    asm volatile("cp.async.cg.shared.global [%0], [%1], 16;" :: "r"(dst), "l"(src));
}

// ---------------- prologue: x->fp16, Wp[0]=I, Wp[1]=dt*W, zero barriers ----
__global__ void prep_kernel(const float* __restrict__ x, const float* __restrict__ W) {
    int i = blockIdx.x * 256 + threadIdx.x;
    g_xh[i] = __float2half(x[i]);
    if (i < DD * DD) {
        int r = i >> 7, c = i & 127;
        g_Wp[0][i] = (r == c) ? 1.0f : 0.0f;
        g_Wp[1][i] = 0.01f * W[i];
    }
    if (i < 4) g_bar[i] = 0;
}

// ---------------- fused powers + combine: ONE launch, 64 CTAs -------------
// Phase ph (m=1,2,4): CTAs [0, m*16) compute Wp[m+i] = Wp[m] @ Wp[i],
//   i = bid/16 + 1, 32x32 tile = bid%16.  Grid spin-barrier between phases.
// Phase 3: CTA b computes P_b = sum c_k A^k -> fp16.
// All 64 CTAs are co-resident (64 <= 148 SMs, 33KB smem) -> no deadlock.
__global__ void __launch_bounds__(256, 1)
powers_combine_kernel() {
    __shared__ float As[DD][33];
    __shared__ float Bs[DD][33];
    int tid = threadIdx.x, bid = blockIdx.x;

#pragma unroll
    for (int ph = 0; ph < 3; ph++) {
        int m = 1 << ph;
        if (bid < m * 16) {
            int i = (bid >> 4) + 1;
            int tile = bid & 15;
            const float* __restrict__ A = g_Wp[m];
            const float* __restrict__ Bm = g_Wp[i];
            float* __restrict__ C = g_Wp[m + i];
            int r0 = (tile >> 2) * 32, c0 = (tile & 3) * 32;

#pragma unroll
            for (int j = 0; j < 4; j++) {
                int q = tid + j * 256;
                int r = q >> 5, k4 = (q & 31) * 4;
                float4 v = *(const float4*)(A + (r0 + r) * DD + k4);
                As[k4 + 0][r] = v.x; As[k4 + 1][r] = v.y;
                As[k4 + 2][r] = v.z; As[k4 + 3][r] = v.w;
            }
#pragma unroll
            for (int j = 0; j < 4; j++) {
                int q = tid + j * 256;
                int k = q >> 3, c4 = (q & 7) * 4;
                float4 v = *(const float4*)(Bm + k * DD + c0 + c4);
                Bs[k][c4 + 0] = v.x; Bs[k][c4 + 1] = v.y;
                Bs[k][c4 + 2] = v.z; Bs[k][c4 + 3] = v.w;
            }
            __syncthreads();

            int r = (tid >> 4) << 1, c = (tid & 15) << 1;
            float a00 = 0, a01 = 0, a10 = 0, a11 = 0;
#pragma unroll
            for (int k = 0; k < DD; k++) {
                float x0 = As[k][r], x1 = As[k][r + 1];
                float y0 = Bs[k][c], y1 = Bs[k][c + 1];
                a00 += x0 * y0; a01 += x0 * y1;
                a10 += x1 * y0; a11 += x1 * y1;
            }
            C[(r0 + r) * DD + c0 + c] = a00;     C[(r0 + r) * DD + c0 + c + 1] = a01;
            C[(r0 + r + 1) * DD + c0 + c] = a10; C[(r0 + r + 1) * DD + c0 + c + 1] = a11;
            __syncthreads();   // smem reuse safety before next phase refill
        }
        // ---- grid barrier ----
        __threadfence();
        __syncthreads();
        if (tid == 0) {
            atomicAdd(&g_bar[ph], 1);
            while (atomicAdd(&g_bar[ph], 0) < 64) { }
        }
        __syncthreads();
        __threadfence();
    }

    // ---- phase 3: combine, one t per CTA ----
    int t = bid;
    float tf = (float)t;
    float coef[NPOW];
    {
        float c = 1.0f;
#pragma unroll
        for (int k = 0; k < NPOW; k++) { coef[k] = c; c *= tf / (float)(k + 1); }
    }
#pragma unroll
    for (int j = 0; j < 64; j++) {
        int i = j * 256 + tid;
        float s = 0.0f;
#pragma unroll
        for (int k = 0; k < NPOW; k++) s += coef[k] * g_Wp[k][i];
        g_Bf[t][i] = __float2half(s);
    }
}

// ---------------- main GEMM: t-batched, double-buffered B ----------------
#define TC 4
#define A_STRIDE 272            // bytes: 128 fp16 + 8 pad
#define SM_A 0
#define SM_B0 (SM_A + 128 * A_STRIDE)         // 34816
#define SM_B1 (SM_B0 + 128 * A_STRIDE)        // 69632
#define SM_TOTAL (SM_B1 + 128 * A_STRIDE)     // 104448

__global__ void __launch_bounds__(256, 2)
gemm_kernel(float* __restrict__ out) {
    extern __shared__ __align__(16) char smem[];
    int tid = threadIdx.x;
    int rb = blockIdx.x, t0 = blockIdx.y * TC;

    const __half* Ah = g_xh + (size_t)rb * 128 * DD;
    uint32_t sb = smem_u32(smem);

#pragma unroll
    for (int j = 0; j < 8; j++) {
        int idx = j * 256 + tid;
        int row = idx >> 4, c = idx & 15;
        *(float4*)(smem + SM_A + row * A_STRIDE + c * 16) =
            *(const float4*)(Ah + row * DD + c * 8);
    }
#pragma unroll
    for (int j = 0; j < 8; j++) {
        int idx = j * 256 + tid;
        int r = idx >> 4, cc = idx & 15;
        cp16(sb + SM_B0 + r * A_STRIDE + cc * 16, g_Bf[t0] + r * DD + cc * 8);
    }
    asm volatile("cp.async.commit_group;" ::: "memory");

    int wid = tid >> 5, lane = tid & 31;
    int wm = wid & 3, wn = wid >> 2;
    uint32_t offA = (uint32_t)((wm * 32 + (lane & 15)) * A_STRIDE + (lane >> 4) * 16);
    uint32_t offB = (uint32_t)(((lane & 7) + ((lane >> 3) & 1) * 8) * A_STRIDE +
                               (wn * 64 + (lane >> 4) * 8) * 2);
    uint32_t Ab = sb + SM_A + offA;
    uint32_t Bbuf[2] = {sb + SM_B0 + offB, sb + SM_B1 + offB};
    uint32_t Braw[2] = {sb + SM_B0, sb + SM_B1};

    int g = lane >> 2, q = lane & 3;
    size_t rowbase = (size_t)rb * 128 + wm * 32;

#pragma unroll
    for (int tt = 0; tt < TC; tt++) {
        if (tt < TC - 1) {
            const __half* Bn = g_Bf[t0 + tt + 1];
            uint32_t dst = Braw[(tt + 1) & 1];
#pragma unroll
            for (int j = 0; j < 8; j++) {
                int idx = j * 256 + tid;
                int r = idx >> 4, cc = idx & 15;
                cp16(dst + r * A_STRIDE + cc * 16, Bn + r * DD + cc * 8);
            }
            asm volatile("cp.async.commit_group;" ::: "memory");
            asm volatile("cp.async.wait_group 1;" ::: "memory");
        } else {
            asm volatile("cp.async.wait_group 0;" ::: "memory");
        }
        __syncthreads();

        uint32_t Bb = Bbuf[tt & 1];
        float acc[2][8][4];
#pragma unroll
        for (int i = 0; i < 2; i++)
#pragma unroll
            for (int j = 0; j < 8; j++)
#pragma unroll
                for (int k = 0; k < 4; k++) acc[i][j][k] = 0.0f;

#pragma unroll
        for (int ks = 0; ks < 8; ks++) {
            uint32_t a0[4], a1[4];
            ldsm4(a0, Ab + ks * 32);
            ldsm4(a1, Ab + ks * 32 + 16 * A_STRIDE);
#pragma unroll
            for (int j = 0; j < 4; j++) {
                uint32_t b[4];
                ldsm4t(b, Bb + ks * 16 * A_STRIDE + j * 32);
                mma16816(acc[0][2 * j],     a0, b[0], b[1]);
                mma16816(acc[0][2 * j + 1], a0, b[2], b[3]);
                mma16816(acc[1][2 * j],     a1, b[0], b[1]);
                mma16816(acc[1][2 * j + 1], a1, b[2], b[3]);
            }
        }

        int t = t0 + tt;
#pragma unroll
        for (int mt = 0; mt < 2; mt++) {
            size_t row = rowbase + mt * 16 + g;
#pragma unroll
            for (int nb = 0; nb < 8; nb++) {
                int col = wn * 64 + nb * 8 + q * 2;
                float* o = out + (row * TT + t) * DD + col;
                *(float2*)o = make_float2(acc[mt][nb][0], acc[mt][nb][1]);
                *(float2*)(o + (size_t)8 * TT * DD) = make_float2(acc[mt][nb][2], acc[mt][nb][3]);
            }
        }
        __syncthreads();
    }
}

// ---------------- launch ----------------
extern "C" void kernel_launch(void* const* d_in, const int* in_sizes, int n_in,
                              void* d_out, int out_size) {
    const float* x = (const float*)d_in[0];
    const float* W = (const float*)d_in[1];
    float* out = (float*)d_out;

    prep_kernel<<<(BB * DD) / 256, 256>>>(x, W);
    powers_combine_kernel<<<64, 256>>>();

    cudaFuncSetAttribute(gemm_kernel, cudaFuncAttributeMaxDynamicSharedMemorySize, SM_TOTAL);
    gemm_kernel<<<dim3(BB / 128, TT / TC), 256, SM_TOTAL>>>(out);
}

// round 11
// speedup vs baseline: 1.1641x; 1.1641x over previous
#include <cuda_runtime.h>
#include <cuda_fp16.h>
#include <cstdint>

#define DD 128
#define TT 64
#define NPOW 9           // A^0 .. A^8 (Taylor K=8; tail ~1e-5 relative)
#define BB 8192

// ---------------- device scratch (no allocs allowed) ----------------
__device__ __align__(1024) __half g_Bf[TT][DD * DD];    // P_t fp16, row-major [k][n]
__device__ __align__(1024) __half g_xh[BB * DD];        // x fp16

// ---------------- helpers ----------------
__device__ __forceinline__ uint32_t smem_u32(const void* p) {
    uint32_t a;
    asm("{ .reg .u64 t; cvta.to.shared.u64 t, %1; cvt.u32.u64 %0, t; }" : "=r"(a) : "l"(p));
    return a;
}
__device__ __forceinline__ void ldsm4(uint32_t* r, uint32_t a) {
    asm volatile("ldmatrix.sync.aligned.m8n8.x4.shared.b16 {%0,%1,%2,%3}, [%4];"
                 : "=r"(r[0]), "=r"(r[1]), "=r"(r[2]), "=r"(r[3]) : "r"(a));
}
__device__ __forceinline__ void ldsm4t(uint32_t* r, uint32_t a) {
    asm volatile("ldmatrix.sync.aligned.m8n8.x4.trans.shared.b16 {%0,%1,%2,%3}, [%4];"
                 : "=r"(r[0]), "=r"(r[1]), "=r"(r[2]), "=r"(r[3]) : "r"(a));
}
__device__ __forceinline__ void mma16816(float* d, const uint32_t* a,
                                         uint32_t b0, uint32_t b1) {
    asm volatile(
        "mma.sync.aligned.m16n8k16.row.col.f32.f16.f16.f32 "
        "{%0,%1,%2,%3}, {%4,%5,%6,%7}, {%8,%9}, {%0,%1,%2,%3};"
        : "+f"(d[0]), "+f"(d[1]), "+f"(d[2]), "+f"(d[3])
        : "r"(a[0]), "r"(a[1]), "r"(a[2]), "r"(a[3]), "r"(b0), "r"(b1));
}
__device__ __forceinline__ void cp16(uint32_t dst, const void* src) {
    asm volatile("cp.async.cg.shared.global [%0], [%1], 16;" :: "r"(dst), "l"(src));
}

// ---------------- fused prologue: ONE launch, two independent paths --------
// CTAs [0,32):   powers-by-columns + combine.  CTA b owns 4 n-columns.
//   M_k = A^k[:, cols] via M_k = A * M_{k-1}  (A resident in smem, no
//   cross-CTA deps, no grid barrier).  Then P_t[:,cols] = sum_k c_{t,k} M_k
//   written straight to g_Bf as fp16.
// CTAs [32,160): x fp32 -> fp16 conversion (8192 elements each).
#define PREP_SMEM (128 * 129 * 4 + NPOW * 128 * 5 * 4)   // At + Mk = 89088 B

__global__ void __launch_bounds__(256, 1)
prep_all_kernel(const float* __restrict__ x, const float* __restrict__ W) {
    extern __shared__ float sm[];
    int tid = threadIdx.x, bid = blockIdx.x;

    if (bid < 32) {
        float* At = sm;                   // [128][129]: At[j][i] = A[i][j]
        float* Mk = sm + 128 * 129;       // [NPOW][128][5] (pad 5 -> conflict-free)

        // load A = dt*W transposed (pad 129 kills STS conflicts)
#pragma unroll
        for (int it = 0; it < 64; it++) {
            int idx = it * 256 + tid;
            int r = idx >> 7, c = idx & 127;
            At[c * 129 + r] = 0.01f * W[idx];
        }
        __syncthreads();

        int i = tid & 127, cp = tid >> 7;     // row i; col pair 2cp, 2cp+1
        int n0 = bid * 4;
        int c0 = 2 * cp, c1 = 2 * cp + 1;

        // M_0 = I[:, cols],  M_1 = A[:, cols]
        Mk[0 * 640 + i * 5 + c0] = (i == n0 + c0) ? 1.0f : 0.0f;
        Mk[0 * 640 + i * 5 + c1] = (i == n0 + c1) ? 1.0f : 0.0f;
        Mk[1 * 640 + i * 5 + c0] = At[(n0 + c0) * 129 + i];
        Mk[1 * 640 + i * 5 + c1] = At[(n0 + c1) * 129 + i];
        __syncthreads();

        // M_k = A * M_{k-1}
        for (int k = 2; k < NPOW; k++) {
            const float* Mp = Mk + (k - 1) * 640;
            float s0 = 0.0f, s1 = 0.0f;
#pragma unroll
            for (int j = 0; j < 128; j++) {
                float a = At[j * 129 + i];
                s0 += a * Mp[j * 5 + c0];
                s1 += a * Mp[j * 5 + c1];
            }
            Mk[k * 640 + i * 5 + c0] = s0;
            Mk[k * 640 + i * 5 + c1] = s1;
            __syncthreads();
        }

        // combine: P_t[i, n0+c] = sum_k (t^k/k!) M_k[i][c]  -> fp16
        for (int t = 0; t < TT; t++) {
            float tf = (float)t, c = 1.0f, s0 = 0.0f, s1 = 0.0f;
#pragma unroll
            for (int k = 0; k < NPOW; k++) {
                s0 += c * Mk[k * 640 + i * 5 + c0];
                s1 += c * Mk[k * 640 + i * 5 + c1];
                c *= tf / (float)(k + 1);
            }
            __half2 h = __floats2half2_rn(s0, s1);
            *(__half2*)(&g_Bf[t][i * DD + n0 + c0]) = h;
        }
    } else {
        // x -> fp16, 8192 elements per CTA, vectorized
        int cb = bid - 32;
        const float4* xs = (const float4*)(x + (size_t)cb * 8192);
        uint2* dst = (uint2*)(g_xh + (size_t)cb * 8192);
#pragma unroll
        for (int j = 0; j < 8; j++) {
            float4 v = xs[j * 256 + tid];
            __half2 h0 = __floats2half2_rn(v.x, v.y);
            __half2 h1 = __floats2half2_rn(v.z, v.w);
            dst[j * 256 + tid] = make_uint2(*(uint32_t*)&h0, *(uint32_t*)&h1);
        }
    }
}

// ---------------- main GEMM: t-batched, double-buffered B (R9, proven) ----
#define TC 4
#define A_STRIDE 272            // bytes: 128 fp16 + 8 pad
#define SM_A 0
#define SM_B0 (SM_A + 128 * A_STRIDE)         // 34816
#define SM_B1 (SM_B0 + 128 * A_STRIDE)        // 69632
#define SM_TOTAL (SM_B1 + 128 * A_STRIDE)     // 104448

__global__ void __launch_bounds__(256, 2)
gemm_kernel(float* __restrict__ out) {
    extern __shared__ __align__(16) char smem[];
    int tid = threadIdx.x;
    int rb = blockIdx.x, t0 = blockIdx.y * TC;

    const __half* Ah = g_xh + (size_t)rb * 128 * DD;
    uint32_t sb = smem_u32(smem);

#pragma unroll
    for (int j = 0; j < 8; j++) {
        int idx = j * 256 + tid;
        int row = idx >> 4, c = idx & 15;
        *(float4*)(smem + SM_A + row * A_STRIDE + c * 16) =
            *(const float4*)(Ah + row * DD + c * 8);
    }
#pragma unroll
    for (int j = 0; j < 8; j++) {
        int idx = j * 256 + tid;
        int r = idx >> 4, cc = idx & 15;
        cp16(sb + SM_B0 + r * A_STRIDE + cc * 16, g_Bf[t0] + r * DD + cc * 8);
    }
    asm volatile("cp.async.commit_group;" ::: "memory");

    int wid = tid >> 5, lane = tid & 31;
    int wm = wid & 3, wn = wid >> 2;
    uint32_t offA = (uint32_t)((wm * 32 + (lane & 15)) * A_STRIDE + (lane >> 4) * 16);
    uint32_t offB = (uint32_t)(((lane & 7) + ((lane >> 3) & 1) * 8) * A_STRIDE +
                               (wn * 64 + (lane >> 4) * 8) * 2);
    uint32_t Ab = sb + SM_A + offA;
    uint32_t Bbuf[2] = {sb + SM_B0 + offB, sb + SM_B1 + offB};
    uint32_t Braw[2] = {sb + SM_B0, sb + SM_B1};

    int g = lane >> 2, q = lane & 3;
    size_t rowbase = (size_t)rb * 128 + wm * 32;

#pragma unroll
    for (int tt = 0; tt < TC; tt++) {
        if (tt < TC - 1) {
            const __half* Bn = g_Bf[t0 + tt + 1];
            uint32_t dst = Braw[(tt + 1) & 1];
#pragma unroll
            for (int j = 0; j < 8; j++) {
                int idx = j * 256 + tid;
                int r = idx >> 4, cc = idx & 15;
                cp16(dst + r * A_STRIDE + cc * 16, Bn + r * DD + cc * 8);
            }
            asm volatile("cp.async.commit_group;" ::: "memory");
            asm volatile("cp.async.wait_group 1;" ::: "memory");
        } else {
            asm volatile("cp.async.wait_group 0;" ::: "memory");
        }
        __syncthreads();

        uint32_t Bb = Bbuf[tt & 1];
        float acc[2][8][4];
#pragma unroll
        for (int i = 0; i < 2; i++)
#pragma unroll
            for (int j = 0; j < 8; j++)
#pragma unroll
                for (int k = 0; k < 4; k++) acc[i][j][k] = 0.0f;

#pragma unroll
        for (int ks = 0; ks < 8; ks++) {
            uint32_t a0[4], a1[4];
            ldsm4(a0, Ab + ks * 32);
            ldsm4(a1, Ab + ks * 32 + 16 * A_STRIDE);
#pragma unroll
            for (int j = 0; j < 4; j++) {
                uint32_t b[4];
                ldsm4t(b, Bb + ks * 16 * A_STRIDE + j * 32);
                mma16816(acc[0][2 * j],     a0, b[0], b[1]);
                mma16816(acc[0][2 * j + 1], a0, b[2], b[3]);
                mma16816(acc[1][2 * j],     a1, b[0], b[1]);
                mma16816(acc[1][2 * j + 1], a1, b[2], b[3]);
            }
        }

        int t = t0 + tt;
#pragma unroll
        for (int mt = 0; mt < 2; mt++) {
            size_t row = rowbase + mt * 16 + g;
#pragma unroll
            for (int nb = 0; nb < 8; nb++) {
                int col = wn * 64 + nb * 8 + q * 2;
                float* o = out + (row * TT + t) * DD + col;
                *(float2*)o = make_float2(acc[mt][nb][0], acc[mt][nb][1]);
                *(float2*)(o + (size_t)8 * TT * DD) = make_float2(acc[mt][nb][2], acc[mt][nb][3]);
            }
        }
        __syncthreads();
    }
}

// ---------------- launch ----------------
extern "C" void kernel_launch(void* const* d_in, const int* in_sizes, int n_in,
                              void* d_out, int out_size) {
    const float* x = (const float*)d_in[0];
    const float* W = (const float*)d_in[1];
    float* out = (float*)d_out;

    cudaFuncSetAttribute(prep_all_kernel, cudaFuncAttributeMaxDynamicSharedMemorySize, PREP_SMEM);
    prep_all_kernel<<<160, 256, PREP_SMEM>>>(x, W);

    cudaFuncSetAttribute(gemm_kernel, cudaFuncAttributeMaxDynamicSharedMemorySize, SM_TOTAL);
    gemm_kernel<<<dim3(BB / 128, TT / TC), 256, SM_TOTAL>>>(out);
}

// round 12
// speedup vs baseline: 1.1649x; 1.0006x over previous
#include <cuda_runtime.h>
#include <cuda_fp16.h>
#include <cstdint>

#define DD 128
#define TT 64
#define NPOW 9           // A^0 .. A^8 (Taylor K=8; tail ~1e-5 relative)
#define BB 8192

// ---------------- device scratch (no allocs allowed) ----------------
__device__ __align__(1024) __half g_Bf[TT][DD * DD];    // P_t fp16, row-major [k][n]
__device__ __align__(1024) __half g_xh[BB * DD];        // x fp16

// ---------------- helpers ----------------
__device__ __forceinline__ uint32_t smem_u32(const void* p) {
    uint32_t a;
    asm("{ .reg .u64 t; cvta.to.shared.u64 t, %1; cvt.u32.u64 %0, t; }" : "=r"(a) : "l"(p));
    return a;
}
__device__ __forceinline__ void ldsm4(uint32_t* r, uint32_t a) {
    asm volatile("ldmatrix.sync.aligned.m8n8.x4.shared.b16 {%0,%1,%2,%3}, [%4];"
                 : "=r"(r[0]), "=r"(r[1]), "=r"(r[2]), "=r"(r[3]) : "r"(a));
}
__device__ __forceinline__ void ldsm4t(uint32_t* r, uint32_t a) {
    asm volatile("ldmatrix.sync.aligned.m8n8.x4.trans.shared.b16 {%0,%1,%2,%3}, [%4];"
                 : "=r"(r[0]), "=r"(r[1]), "=r"(r[2]), "=r"(r[3]) : "r"(a));
}
__device__ __forceinline__ void mma16816(float* d, const uint32_t* a,
                                         uint32_t b0, uint32_t b1) {
    asm volatile(
        "mma.sync.aligned.m16n8k16.row.col.f32.f16.f16.f32 "
        "{%0,%1,%2,%3}, {%4,%5,%6,%7}, {%8,%9}, {%0,%1,%2,%3};"
        : "+f"(d[0]), "+f"(d[1]), "+f"(d[2]), "+f"(d[3])
        : "r"(a[0]), "r"(a[1]), "r"(a[2]), "r"(a[3]), "r"(b0), "r"(b1));
}
__device__ __forceinline__ void cp16(uint32_t dst, const void* src) {
    asm volatile("cp.async.cg.shared.global [%0], [%1], 16;" :: "r"(dst), "l"(src));
}

// ---------------- fused prologue: ONE launch, two independent paths --------
// CTAs [0,32): powers-by-columns + combine. CTA b owns 4 n-columns of P_t.
//   M_k = A * M_{k-1} with A row-major in smem (pad 132 -> conflict-free
//   LDS.128 of own row), M_{k-1} broadcast float2.  Thread keeps its
//   M_k[i][c0,c1] for ALL k in registers -> combine is pure FFMA.
// CTAs [32,160): x fp32 -> fp16 conversion.
#define A_PAD 132
#define PREP_SMEM (128 * A_PAD * 4 + NPOW * 128 * 4 * 4)   // 67584 + 18432 = 86016

__global__ void __launch_bounds__(256, 1)
prep_all_kernel(const float* __restrict__ x, const float* __restrict__ W) {
    extern __shared__ float sm[];
    int tid = threadIdx.x, bid = blockIdx.x;

    if (bid < 32) {
        float* Arow = sm;                    // [i][132]: A[i][j] = dt*W[i][j]
        float* Mk = sm + 128 * A_PAD;        // [k][j][4]

#pragma unroll
        for (int it = 0; it < 64; it++) {
            int idx = it * 256 + tid;
            int r = idx >> 7, c = idx & 127;
            Arow[r * A_PAD + c] = 0.01f * W[idx];
        }
        __syncthreads();

        int i = tid & 127, cp = tid >> 7;    // row i; cols c0=2cp, c0+1
        int n0 = bid * 4, c0 = 2 * cp;

        float m[NPOW][2];                    // M_k[i][c0], M_k[i][c1]
        m[0][0] = (i == n0 + c0) ? 1.0f : 0.0f;
        m[0][1] = (i == n0 + c0 + 1) ? 1.0f : 0.0f;
        m[1][0] = Arow[i * A_PAD + n0 + c0];
        m[1][1] = Arow[i * A_PAD + n0 + c0 + 1];
        *(float2*)&Mk[1 * 512 + i * 4 + c0] = make_float2(m[1][0], m[1][1]);
        __syncthreads();

        for (int k = 2; k < NPOW; k++) {
            const float* Mp = Mk + (k - 1) * 512;
            const float* ar = Arow + i * A_PAD;
            float s0 = 0.0f, s1 = 0.0f;
#pragma unroll
            for (int j = 0; j < 128; j += 4) {
                float4 a = *(const float4*)(ar + j);
                float2 p0 = *(const float2*)(Mp + (j + 0) * 4 + c0);
                float2 p1 = *(const float2*)(Mp + (j + 1) * 4 + c0);
                float2 p2 = *(const float2*)(Mp + (j + 2) * 4 + c0);
                float2 p3 = *(const float2*)(Mp + (j + 3) * 4 + c0);
                s0 += a.x * p0.x; s1 += a.x * p0.y;
                s0 += a.y * p1.x; s1 += a.y * p1.y;
                s0 += a.z * p2.x; s1 += a.z * p2.y;
                s0 += a.w * p3.x; s1 += a.w * p3.y;
            }
            m[k][0] = s0; m[k][1] = s1;
            *(float2*)&Mk[k * 512 + i * 4 + c0] = make_float2(s0, s1);
            __syncthreads();
        }

        // combine from registers: P_t[i, n0+c] = sum_k (t^k/k!) m[k]
        for (int t = 0; t < TT; t++) {
            float tf = (float)t, c = 1.0f, s0 = 0.0f, s1 = 0.0f;
#pragma unroll
            for (int k = 0; k < NPOW; k++) {
                s0 += c * m[k][0];
                s1 += c * m[k][1];
                c *= tf / (float)(k + 1);
            }
            *(__half2*)(&g_Bf[t][i * DD + n0 + c0]) = __floats2half2_rn(s0, s1);
        }
    } else {
        // x -> fp16, 8192 elements per CTA, vectorized
        int cb = bid - 32;
        const float4* xs = (const float4*)(x + (size_t)cb * 8192);
        uint2* dst = (uint2*)(g_xh + (size_t)cb * 8192);
#pragma unroll
        for (int j = 0; j < 8; j++) {
            float4 v = xs[j * 256 + tid];
            __half2 h0 = __floats2half2_rn(v.x, v.y);
            __half2 h1 = __floats2half2_rn(v.z, v.w);
            dst[j * 256 + tid] = make_uint2(*(uint32_t*)&h0, *(uint32_t*)&h1);
        }
    }
}

// ---------------- main GEMM: t-batched, double-buffered B ----------------
#define TC 2
#define A_STRIDE 272            // bytes: 128 fp16 + 8 pad
#define SM_A 0
#define SM_B0 (SM_A + 128 * A_STRIDE)         // 34816
#define SM_B1 (SM_B0 + 128 * A_STRIDE)        // 69632
#define SM_TOTAL (SM_B1 + 128 * A_STRIDE)     // 104448

__global__ void __launch_bounds__(256, 2)
gemm_kernel(float* __restrict__ out) {
    extern __shared__ __align__(16) char smem[];
    int tid = threadIdx.x;
    int rb = blockIdx.x, t0 = blockIdx.y * TC;

    const __half* Ah = g_xh + (size_t)rb * 128 * DD;
    uint32_t sb = smem_u32(smem);

#pragma unroll
    for (int j = 0; j < 8; j++) {
        int idx = j * 256 + tid;
        int row = idx >> 4, c = idx & 15;
        *(float4*)(smem + SM_A + row * A_STRIDE + c * 16) =
            *(const float4*)(Ah + row * DD + c * 8);
    }
#pragma unroll
    for (int j = 0; j < 8; j++) {
        int idx = j * 256 + tid;
        int r = idx >> 4, cc = idx & 15;
        cp16(sb + SM_B0 + r * A_STRIDE + cc * 16, g_Bf[t0] + r * DD + cc * 8);
    }
    asm volatile("cp.async.commit_group;" ::: "memory");

    int wid = tid >> 5, lane = tid & 31;
    int wm = wid & 3, wn = wid >> 2;
    uint32_t offA = (uint32_t)((wm * 32 + (lane & 15)) * A_STRIDE + (lane >> 4) * 16);
    uint32_t offB = (uint32_t)(((lane & 7) + ((lane >> 3) & 1) * 8) * A_STRIDE +
                               (wn * 64 + (lane >> 4) * 8) * 2);
    uint32_t Ab = sb + SM_A + offA;
    uint32_t Bbuf[2] = {sb + SM_B0 + offB, sb + SM_B1 + offB};
    uint32_t Braw[2] = {sb + SM_B0, sb + SM_B1};

    int g = lane >> 2, q = lane & 3;
    size_t rowbase = (size_t)rb * 128 + wm * 32;

#pragma unroll
    for (int tt = 0; tt < TC; tt++) {
        if (tt < TC - 1) {
            const __half* Bn = g_Bf[t0 + tt + 1];
            uint32_t dst = Braw[(tt + 1) & 1];
#pragma unroll
            for (int j = 0; j < 8; j++) {
                int idx = j * 256 + tid;
                int r = idx >> 4, cc = idx & 15;
                cp16(dst + r * A_STRIDE + cc * 16, Bn + r * DD + cc * 8);
            }
            asm volatile("cp.async.commit_group;" ::: "memory");
            asm volatile("cp.async.wait_group 1;" ::: "memory");
        } else {
            asm volatile("cp.async.wait_group 0;" ::: "memory");
        }
        __syncthreads();

        uint32_t Bb = Bbuf[tt & 1];
        float acc[2][8][4];
#pragma unroll
        for (int i = 0; i < 2; i++)
#pragma unroll
            for (int j = 0; j < 8; j++)
#pragma unroll
                for (int k = 0; k < 4; k++) acc[i][j][k] = 0.0f;

#pragma unroll
        for (int ks = 0; ks < 8; ks++) {
            uint32_t a0[4], a1[4];
            ldsm4(a0, Ab + ks * 32);
            ldsm4(a1, Ab + ks * 32 + 16 * A_STRIDE);
#pragma unroll
            for (int j = 0; j < 4; j++) {
                uint32_t b[4];
                ldsm4t(b, Bb + ks * 16 * A_STRIDE + j * 32);
                mma16816(acc[0][2 * j],     a0, b[0], b[1]);
                mma16816(acc[0][2 * j + 1], a0, b[2], b[3]);
                mma16816(acc[1][2 * j],     a1, b[0], b[1]);
                mma16816(acc[1][2 * j + 1], a1, b[2], b[3]);
            }
        }

        int t = t0 + tt;
#pragma unroll
        for (int mt = 0; mt < 2; mt++) {
            size_t row = rowbase + mt * 16 + g;
#pragma unroll
            for (int nb = 0; nb < 8; nb++) {
                int col = wn * 64 + nb * 8 + q * 2;
                float* o = out + (row * TT + t) * DD + col;
                *(float2*)o = make_float2(acc[mt][nb][0], acc[mt][nb][1]);
                *(float2*)(o + (size_t)8 * TT * DD) = make_float2(acc[mt][nb][2], acc[mt][nb][3]);
            }
        }
        __syncthreads();
    }
}

// ---------------- launch ----------------
extern "C" void kernel_launch(void* const* d_in, const int* in_sizes, int n_in,
                              void* d_out, int out_size) {
    const float* x = (const float*)d_in[0];
    const float* W = (const float*)d_in[1];
    float* out = (float*)d_out;

    cudaFuncSetAttribute(prep_all_kernel, cudaFuncAttributeMaxDynamicSharedMemorySize, PREP_SMEM);
    prep_all_kernel<<<160, 256, PREP_SMEM>>>(x, W);

    cudaFuncSetAttribute(gemm_kernel, cudaFuncAttributeMaxDynamicSharedMemorySize, SM_TOTAL);
    gemm_kernel<<<dim3(BB / 128, TT / TC), 256, SM_TOTAL>>>(out);
}

// round 13
// speedup vs baseline: 1.2303x; 1.0561x over previous
#include <cuda_runtime.h>
#include <cuda_fp16.h>
#include <cstdint>

#define DD 128
#define TT 64
#define NPOW 9           // A^0 .. A^8 (Taylor K=8; tail ~1e-5 relative)
#define BB 8192

// ---------------- device scratch (no allocs allowed) ----------------
// g_Bf[t] holds P_t TRANSPOSED: [n][k] n-major (so prep writes are coalesced
// and GEMM consumes via non-trans ldmatrix).
__device__ __align__(1024) __half g_Bf[TT][DD * DD];
__device__ __align__(1024) __half g_xh[BB * DD];        // x fp16

// ---------------- helpers ----------------
__device__ __forceinline__ uint32_t smem_u32(const void* p) {
    uint32_t a;
    asm("{ .reg .u64 t; cvta.to.shared.u64 t, %1; cvt.u32.u64 %0, t; }" : "=r"(a) : "l"(p));
    return a;
}
__device__ __forceinline__ void ldsm4(uint32_t* r, uint32_t a) {
    asm volatile("ldmatrix.sync.aligned.m8n8.x4.shared.b16 {%0,%1,%2,%3}, [%4];"
                 : "=r"(r[0]), "=r"(r[1]), "=r"(r[2]), "=r"(r[3]) : "r"(a));
}
__device__ __forceinline__ void mma16816(float* d, const uint32_t* a,
                                         uint32_t b0, uint32_t b1) {
    asm volatile(
        "mma.sync.aligned.m16n8k16.row.col.f32.f16.f16.f32 "
        "{%0,%1,%2,%3}, {%4,%5,%6,%7}, {%8,%9}, {%0,%1,%2,%3};"
        : "+f"(d[0]), "+f"(d[1]), "+f"(d[2]), "+f"(d[3])
        : "r"(a[0]), "r"(a[1]), "r"(a[2]), "r"(a[3]), "r"(b0), "r"(b1));
}
__device__ __forceinline__ void cp16(uint32_t dst, const void* src) {
    asm volatile("cp.async.cg.shared.global [%0], [%1], 16;" :: "r"(dst), "l"(src));
}

// ---------------- fused prologue: ONE launch, two independent paths --------
// CTAs [0,32): powers-by-columns + combine. CTA b owns P columns n0..n0+3
//   = Pt rows n0..n0+3 -> COALESCED stores into transposed g_Bf.
// CTAs [32,160): x fp32 -> fp16 conversion.
#define A_PAD 132
#define PREP_SMEM (128 * A_PAD * 4 + NPOW * 128 * 4 * 4)   // 86016

__global__ void __launch_bounds__(256, 1)
prep_all_kernel(const float* __restrict__ x, const float* __restrict__ W) {
    extern __shared__ float sm[];
    int tid = threadIdx.x, bid = blockIdx.x;

    if (bid < 32) {
        float* Arow = sm;                    // [i][132]: A[i][j] = dt*W[i][j]
        float* Mk = sm + 128 * A_PAD;        // [k][j][4]

#pragma unroll
        for (int it = 0; it < 64; it++) {
            int idx = it * 256 + tid;
            int r = idx >> 7, c = idx & 127;
            Arow[r * A_PAD + c] = 0.01f * W[idx];
        }
        __syncthreads();

        int i = tid & 127, cp = tid >> 7;    // row i of P; cols c0=2cp, c0+1
        int n0 = bid * 4, c0 = 2 * cp;

        float m[NPOW][2];                    // M_k[i][c0], M_k[i][c1]
        m[0][0] = (i == n0 + c0) ? 1.0f : 0.0f;
        m[0][1] = (i == n0 + c0 + 1) ? 1.0f : 0.0f;
        m[1][0] = Arow[i * A_PAD + n0 + c0];
        m[1][1] = Arow[i * A_PAD + n0 + c0 + 1];
        *(float2*)&Mk[1 * 512 + i * 4 + c0] = make_float2(m[1][0], m[1][1]);
        __syncthreads();

        for (int k = 2; k < NPOW; k++) {
            const float* Mp = Mk + (k - 1) * 512;
            const float* ar = Arow + i * A_PAD;
            float s0 = 0.0f, s1 = 0.0f;
#pragma unroll
            for (int j = 0; j < 128; j += 4) {
                float4 a = *(const float4*)(ar + j);
                float2 p0 = *(const float2*)(Mp + (j + 0) * 4 + c0);
                float2 p1 = *(const float2*)(Mp + (j + 1) * 4 + c0);
                float2 p2 = *(const float2*)(Mp + (j + 2) * 4 + c0);
                float2 p3 = *(const float2*)(Mp + (j + 3) * 4 + c0);
                s0 += a.x * p0.x; s1 += a.x * p0.y;
                s0 += a.y * p1.x; s1 += a.y * p1.y;
                s0 += a.z * p2.x; s1 += a.z * p2.y;
                s0 += a.w * p3.x; s1 += a.w * p3.y;
            }
            m[k][0] = s0; m[k][1] = s1;
            *(float2*)&Mk[k * 512 + i * 4 + c0] = make_float2(s0, s1);
            __syncthreads();
        }

        // combine from registers, store TRANSPOSED (coalesced along i):
        // g_Bf[t][(n0+c)*DD + i] = P_t[i][n0+c]
        for (int t = 0; t < TT; t++) {
            float tf = (float)t, c = 1.0f, s0 = 0.0f, s1 = 0.0f;
#pragma unroll
            for (int k = 0; k < NPOW; k++) {
                s0 += c * m[k][0];
                s1 += c * m[k][1];
                c *= tf / (float)(k + 1);
            }
            g_Bf[t][(n0 + c0) * DD + i]     = __float2half_rn(s0);
            g_Bf[t][(n0 + c0 + 1) * DD + i] = __float2half_rn(s1);
        }
    } else {
        int cb = bid - 32;
        const float4* xs = (const float4*)(x + (size_t)cb * 8192);
        uint2* dst = (uint2*)(g_xh + (size_t)cb * 8192);
#pragma unroll
        for (int j = 0; j < 8; j++) {
            float4 v = xs[j * 256 + tid];
            __half2 h0 = __floats2half2_rn(v.x, v.y);
            __half2 h1 = __floats2half2_rn(v.z, v.w);
            dst[j * 256 + tid] = make_uint2(*(uint32_t*)&h0, *(uint32_t*)&h1);
        }
    }
}

// ---------------- main GEMM: t-batched, double-buffered B ----------------
// B tile is Pt [n][k] n-major: consumed via NON-trans ldmatrix.
#define TC 2
#define A_STRIDE 272            // bytes: 128 fp16 + 8 pad
#define SM_A 0
#define SM_B0 (SM_A + 128 * A_STRIDE)         // 34816
#define SM_B1 (SM_B0 + 128 * A_STRIDE)        // 69632
#define SM_TOTAL (SM_B1 + 128 * A_STRIDE)     // 104448

__global__ void __launch_bounds__(256, 2)
gemm_kernel(float* __restrict__ out) {
    extern __shared__ __align__(16) char smem[];
    int tid = threadIdx.x;
    int rb = blockIdx.x, t0 = blockIdx.y * TC;

    const __half* Ah = g_xh + (size_t)rb * 128 * DD;
    uint32_t sb = smem_u32(smem);

#pragma unroll
    for (int j = 0; j < 8; j++) {
        int idx = j * 256 + tid;
        int row = idx >> 4, c = idx & 15;
        *(float4*)(smem + SM_A + row * A_STRIDE + c * 16) =
            *(const float4*)(Ah + row * DD + c * 8);
    }
#pragma unroll
    for (int j = 0; j < 8; j++) {
        int idx = j * 256 + tid;
        int r = idx >> 4, cc = idx & 15;
        cp16(sb + SM_B0 + r * A_STRIDE + cc * 16, g_Bf[t0] + r * DD + cc * 8);
    }
    asm volatile("cp.async.commit_group;" ::: "memory");

    int wid = tid >> 5, lane = tid & 31;
    int wm = wid & 3, wn = wid >> 2;
    uint32_t offA = (uint32_t)((wm * 32 + (lane & 15)) * A_STRIDE + (lane >> 4) * 16);
    // non-trans B fragment addresses on [n][k] tile:
    //   n_row = (lane&7) + (lane bit4 ? 8 : 0),  k byte off = (lane bit3 ? 16 : 0)
    uint32_t offB = (uint32_t)((wn * 64 + (lane & 7) + ((lane >> 1) & 8)) * A_STRIDE +
                               (lane & 8) * 2);
    uint32_t Ab = sb + SM_A + offA;
    uint32_t Bbuf[2] = {sb + SM_B0 + offB, sb + SM_B1 + offB};
    uint32_t Braw[2] = {sb + SM_B0, sb + SM_B1};

    int g = lane >> 2, q = lane & 3;
    size_t rowbase = (size_t)rb * 128 + wm * 32;

#pragma unroll
    for (int tt = 0; tt < TC; tt++) {
        if (tt < TC - 1) {
            const __half* Bn = g_Bf[t0 + tt + 1];
            uint32_t dst = Braw[(tt + 1) & 1];
#pragma unroll
            for (int j = 0; j < 8; j++) {
                int idx = j * 256 + tid;
                int r = idx >> 4, cc = idx & 15;
                cp16(dst + r * A_STRIDE + cc * 16, Bn + r * DD + cc * 8);
            }
            asm volatile("cp.async.commit_group;" ::: "memory");
            asm volatile("cp.async.wait_group 1;" ::: "memory");
        } else {
            asm volatile("cp.async.wait_group 0;" ::: "memory");
        }
        __syncthreads();

        uint32_t Bb = Bbuf[tt & 1];
        float acc[2][8][4];
#pragma unroll
        for (int i = 0; i < 2; i++)
#pragma unroll
            for (int j = 0; j < 8; j++)
#pragma unroll
                for (int k = 0; k < 4; k++) acc[i][j][k] = 0.0f;

#pragma unroll
        for (int ks = 0; ks < 8; ks++) {
            uint32_t a0[4], a1[4];
            ldsm4(a0, Ab + ks * 32);
            ldsm4(a1, Ab + ks * 32 + 16 * A_STRIDE);
#pragma unroll
            for (int j = 0; j < 4; j++) {    // n-groups of 16
                uint32_t b[4];
                ldsm4(b, Bb + j * 16 * A_STRIDE + ks * 32);
                mma16816(acc[0][2 * j],     a0, b[0], b[1]);
                mma16816(acc[0][2 * j + 1], a0, b[2], b[3]);
                mma16816(acc[1][2 * j],     a1, b[0], b[1]);
                mma16816(acc[1][2 * j + 1], a1, b[2], b[3]);
            }
        }

        int t = t0 + tt;
#pragma unroll
        for (int mt = 0; mt < 2; mt++) {
            size_t row = rowbase + mt * 16 + g;
#pragma unroll
            for (int nb = 0; nb < 8; nb++) {
                int col = wn * 64 + nb * 8 + q * 2;
                float* o = out + (row * TT + t) * DD + col;
                *(float2*)o = make_float2(acc[mt][nb][0], acc[mt][nb][1]);
                *(float2*)(o + (size_t)8 * TT * DD) = make_float2(acc[mt][nb][2], acc[mt][nb][3]);
            }
        }
        __syncthreads();
    }
}

// ---------------- launch ----------------
extern "C" void kernel_launch(void* const* d_in, const int* in_sizes, int n_in,
                              void* d_out, int out_size) {
    const float* x = (const float*)d_in[0];
    const float* W = (const float*)d_in[1];
    float* out = (float*)d_out;

    cudaFuncSetAttribute(prep_all_kernel, cudaFuncAttributeMaxDynamicSharedMemorySize, PREP_SMEM);
    prep_all_kernel<<<160, 256, PREP_SMEM>>>(x, W);

    cudaFuncSetAttribute(gemm_kernel, cudaFuncAttributeMaxDynamicSharedMemorySize, SM_TOTAL);
    gemm_kernel<<<dim3(BB / 128, TT / TC), 256, SM_TOTAL>>>(out);
}